// round 1
// baseline (speedup 1.0000x reference)
#include <cuda_runtime.h>

// ---------------- problem constants ----------------
#define N_PATCH   40000
#define GRP       4
#define DIM       400          // 16*5*5
#define KC        64           // clusters
#define EPOCHS    10
#define ROWSTRIDE 1600         // GRP*DIM floats per patch row

// assign-kernel tiling
#define TM   128               // patches per CTA
#define DK   40                // k-chunk (400 = 10*40)
#define APAD 44                // padded smem row (16B aligned, conflict-friendly)

// sum-kernel partition
#define SUM_CTAS 74
#define PPC      541           // ceil(40000/74)

// ---------------- device state ----------------
__device__ float g_centroids[GRP * KC * DIM];
__device__ float g_c2[GRP * KC];
__device__ int   g_labels[GRP * N_PATCH];
__device__ float g_sums[GRP * KC * DIM];
__device__ float g_counts[GRP * KC];

// ---------------- kernels ----------------
__global__ void copy_init_kernel(const float* __restrict__ cin) {
    int i = blockIdx.x * blockDim.x + threadIdx.x;
    if (i < GRP * KC * DIM) g_centroids[i] = cin[i];
}

// one block per (g,k): compute c2 = 0.5*||c||^2, zero sums row + count
__global__ void prep_kernel() {
    int b = blockIdx.x;                 // g*KC + k
    const float* c = &g_centroids[b * DIM];
    float s = 0.f;
    for (int d = threadIdx.x; d < DIM; d += 128) {
        float v = c[d];
        s += v * v;
        g_sums[b * DIM + d] = 0.f;
    }
#pragma unroll
    for (int o = 16; o; o >>= 1) s += __shfl_down_sync(0xffffffffu, s, o);
    __shared__ float ws[4];
    if ((threadIdx.x & 31) == 0) ws[threadIdx.x >> 5] = s;
    __syncthreads();
    if (threadIdx.x == 0) {
        g_c2[b] = 0.5f * (ws[0] + ws[1] + ws[2] + ws[3]);
        g_counts[b] = 0.f;
    }
}

// scores = C . P^T tile (128 patches x 64 clusters, K=400), fused argmax -> labels
__global__ void __launch_bounds__(256, 2) assign_kernel(const float* __restrict__ patches) {
    __shared__ float smem[TM * APAD + KC * APAD];   // union: tiles OR Cs[128][65]
    __shared__ float c2s[KC];
    float* As = smem;
    float* Bs = smem + TM * APAD;

    const int g    = blockIdx.y;
    const int row0 = blockIdx.x * TM;
    const int tid  = threadIdx.x;
    const int tx   = tid & 15;
    const int ty   = tid >> 4;

    if (tid < KC) c2s[tid] = g_c2[g * KC + tid];

    float acc[8][4];
#pragma unroll
    for (int i = 0; i < 8; i++)
#pragma unroll
        for (int j = 0; j < 4; j++) acc[i][j] = 0.f;

    const float* cbase = &g_centroids[g * KC * DIM];

    for (int kk = 0; kk < DIM; kk += DK) {
        // load A chunk: 128 rows x 40 floats = 1280 float4
#pragma unroll
        for (int l = 0; l < 5; l++) {
            int idx = tid + l * 256;
            int r = idx / 10, c = idx % 10;
            int n = row0 + r;
            float4 v = make_float4(0.f, 0.f, 0.f, 0.f);
            if (n < N_PATCH)
                v = *(const float4*)&patches[(size_t)n * ROWSTRIDE + g * DIM + kk + c * 4];
            *(float4*)&As[r * APAD + c * 4] = v;
        }
        // load B chunk: 64 rows x 40 floats = 640 float4
        for (int idx = tid; idx < 640; idx += 256) {
            int r = idx / 10, c = idx % 10;
            *(float4*)&Bs[r * APAD + c * 4] =
                *(const float4*)&cbase[r * DIM + kk + c * 4];
        }
        __syncthreads();

#pragma unroll
        for (int k = 0; k < DK; k += 4) {
            float4 a[8], b[4];
#pragma unroll
            for (int i = 0; i < 8; i++)
                a[i] = *(float4*)&As[(ty + 16 * i) * APAD + k];
#pragma unroll
            for (int j = 0; j < 4; j++)
                b[j] = *(float4*)&Bs[(tx + 16 * j) * APAD + k];
#pragma unroll
            for (int i = 0; i < 8; i++)
#pragma unroll
                for (int j = 0; j < 4; j++) {
                    float t = acc[i][j];
                    t = fmaf(a[i].x, b[j].x, t);
                    t = fmaf(a[i].y, b[j].y, t);
                    t = fmaf(a[i].z, b[j].z, t);
                    t = fmaf(a[i].w, b[j].w, t);
                    acc[i][j] = t;
                }
        }
        __syncthreads();
    }

    // epilogue: stage scores - c2 into smem, then per-row argmax (first-max ties)
    float* Cs = smem;   // [128][65]
#pragma unroll
    for (int i = 0; i < 8; i++)
#pragma unroll
        for (int j = 0; j < 4; j++)
            Cs[(ty + 16 * i) * 65 + (tx + 16 * j)] = acc[i][j] - c2s[tx + 16 * j];
    __syncthreads();

    if (tid < TM) {
        int n = row0 + tid;
        if (n < N_PATCH) {
            const float* row = &Cs[tid * 65];
            float best = row[0];
            int bi = 0;
#pragma unroll
            for (int k2 = 1; k2 < KC; k2++) {
                float v = row[k2];
                if (v > best) { best = v; bi = k2; }
            }
            g_labels[g * N_PATCH + n] = bi;
        }
    }
}

// per-CTA K*D partial sums in dynamic smem, atomic flush
__global__ void sum_kernel(const float* __restrict__ patches) {
    extern __shared__ float ssum[];                 // KC*DIM sums + KC counts
    float* acc = ssum;
    float* cnt = ssum + KC * DIM;
    const int g   = blockIdx.y;
    const int s   = blockIdx.x;
    const int tid = threadIdx.x;

    for (int i = tid; i < KC * DIM; i += 256) acc[i] = 0.f;
    if (tid < KC) cnt[tid] = 0.f;
    __syncthreads();

    const int start = s * PPC;
    const int end   = min(start + PPC, N_PATCH);
    const int* lbl  = &g_labels[g * N_PATCH];

    for (int nb = start; nb < end; nb += 8) {
        int nu = min(8, end - nb);
        int   l[8];
        float v0[8], v1[8];
#pragma unroll
        for (int u = 0; u < 8; u++) {
            bool ok = (u < nu);
            int nn = ok ? (nb + u) : start;
            l[u] = lbl[nn];
            const float* p = &patches[(size_t)nn * ROWSTRIDE + g * DIM];
            v0[u] = ok ? p[tid] : 0.f;
            v1[u] = (ok && tid < DIM - 256) ? p[256 + tid] : 0.f;
        }
#pragma unroll
        for (int u = 0; u < 8; u++) {
            if (u < nu) {
                acc[l[u] * DIM + tid] += v0[u];
                if (tid < DIM - 256) acc[l[u] * DIM + 256 + tid] += v1[u];
                if (tid == 0) cnt[l[u]] += 1.f;
            }
        }
    }
    __syncthreads();

    for (int i = tid; i < KC * DIM; i += 256)
        atomicAdd(&g_sums[(size_t)g * KC * DIM + i], acc[i]);
    if (tid < KC) atomicAdd(&g_counts[g * KC + tid], cnt[tid]);
}

// new centroids = sums / max(count,1); zero cluster k if empty in ANY group
__global__ void finalize_kernel(float* out) {
    int b = blockIdx.x;            // g*KC + k
    int k = b % KC;
    __shared__ float denom_s;
    __shared__ int   bad_s;
    if (threadIdx.x == 0) {
        bool bad = false;
        for (int gg = 0; gg < GRP; gg++)
            if (g_counts[gg * KC + k] == 0.f) bad = true;
        float c = g_counts[b];
        denom_s = (c == 0.f) ? 1.f : c;
        bad_s = bad ? 1 : 0;
    }
    __syncthreads();
    float denom = denom_s;
    int bad = bad_s;
    for (int d = threadIdx.x; d < DIM; d += 128) {
        float v = bad ? 0.f : (g_sums[b * DIM + d] / denom);
        g_centroids[b * DIM + d] = v;
        if (out) out[b * DIM + d] = v;
    }
}

// ---------------- launch ----------------
extern "C" void kernel_launch(void* const* d_in, const int* in_sizes, int n_in,
                              void* d_out, int out_size) {
    const float* patches = (const float*)d_in[0];
    const float* cinit   = (const float*)d_in[1];
    float* out = (float*)d_out;

    const int sum_smem = (KC * DIM + KC) * (int)sizeof(float);   // 102,656 B
    cudaFuncSetAttribute(sum_kernel, cudaFuncAttributeMaxDynamicSharedMemorySize, sum_smem);

    copy_init_kernel<<<(GRP * KC * DIM + 255) / 256, 256>>>(cinit);

    for (int e = 0; e < EPOCHS; e++) {
        prep_kernel<<<GRP * KC, 128>>>();
        assign_kernel<<<dim3((N_PATCH + TM - 1) / TM, GRP), 256>>>(patches);
        sum_kernel<<<dim3(SUM_CTAS, GRP), 256, sum_smem>>>(patches);
        finalize_kernel<<<GRP * KC, 128>>>(e == EPOCHS - 1 ? out : nullptr);
    }
}